// round 11
// baseline (speedup 1.0000x reference)
#include <cuda_runtime.h>
#include <cuda_bf16.h>
#include <cuda_fp16.h>
#include <cstdint>

// ---------------------------------------------------------------------------
// Problem dims (fixed by the dataset)
// ---------------------------------------------------------------------------
#define D_     2048
#define K_     2048
#define NTOT   6144            // 3*D
#define M_     8192            // 4*2048
#define R_     8

#define KC        64           // k-elems per chunk (128B fp16 rows, SW128)
#define NKC       32           // K_/KC
#define MHALVES   64           // M_/128
#define NHALVES   48           // NTOT/128
#define TILE_BYTES  16384      // one 128x64 fp16 tile (SW128 image)
#define STAGES    3
#define STAGE_BYTES 32768      // A (16K) + B (16K)
#define SMEM_REQ  (STAGES * STAGE_BYTES + 1024)   // 99328 -> 2 CTAs/SM

// fp16 blobs, stored as byte-exact SW128 tile images:
// blob[half*32 + kc] = 16KB tile; byte (r, c) at sw128(r*128 + c*2)
__device__ __align__(128) unsigned char g_X[(size_t)MHALVES * NKC * TILE_BYTES]; // 32 MB
__device__ __align__(128) unsigned char g_W[(size_t)NHALVES * NKC * TILE_BYTES]; // 24 MB

// ---------------------------------------------------------------------------
// PTX helpers (baseline sm_80/90 features only)
// ---------------------------------------------------------------------------
__device__ __forceinline__ uint32_t smem_u32(const void* p) {
    uint32_t a;
    asm("{ .reg .u64 t; cvta.to.shared.u64 t, %1; cvt.u32.u64 %0, t; }" : "=r"(a) : "l"(p));
    return a;
}
#define CP_ASYNC16(s, g) \
    asm volatile("cp.async.cg.shared.global [%0], [%1], 16;" :: "r"(s), "l"(g) : "memory")
#define CP_COMMIT() asm volatile("cp.async.commit_group;" ::: "memory")
#define CP_WAIT(n)  asm volatile("cp.async.wait_group %0;" :: "n"(n) : "memory")

#define LDSM_X4(r0, r1, r2, r3, a) \
    asm volatile("ldmatrix.sync.aligned.m8n8.x4.shared.b16 {%0,%1,%2,%3}, [%4];" \
                 : "=r"(r0), "=r"(r1), "=r"(r2), "=r"(r3) : "r"(a))

#define MMA_F16(d, a0, a1, a2, a3, b0, b1) \
    asm volatile("mma.sync.aligned.m16n8k16.row.col.f32.f16.f16.f32 " \
                 "{%0,%1,%2,%3}, {%4,%5,%6,%7}, {%8,%9}, {%0,%1,%2,%3};" \
                 : "+f"((d)[0]), "+f"((d)[1]), "+f"((d)[2]), "+f"((d)[3]) \
                 : "r"(a0), "r"(a1), "r"(a2), "r"(a3), "r"(b0), "r"(b1))

__device__ __forceinline__ uint32_t swz(uint32_t off) { return off ^ ((off >> 3) & 0x70u); }

// ---------------------------------------------------------------------------
// Convert kernels: fp32 -> fp16 in pre-swizzled blob layout.
// Two separate launches — measured faster than the fused variant (R9).
// ---------------------------------------------------------------------------
__device__ __forceinline__ void cvt8_store(const float* xs, unsigned char* blobbase,
                                           unsigned m_in_half, unsigned k_in_chunk) {
    union { unsigned short s[8]; uint4 v; } h;
#pragma unroll
    for (int j = 0; j < 8; j++) h.s[j] = __half_as_ushort(__float2half_rn(xs[j]));
    unsigned off = (m_in_half << 7) | (k_in_chunk << 1);
    *(uint4*)(blobbase + swz(off)) = h.v;
}

__global__ void __launch_bounds__(256) convX(const float* __restrict__ X) {
    unsigned idx = blockIdx.x * 256u + threadIdx.x;
    unsigned m  = idx >> 8;
    unsigned k0 = (idx & 255u) << 3;
    const float4* src = (const float4*)(X + (size_t)m * K_ + k0);
    float4 v0 = src[0], v1 = src[1];
    float xs[8] = {v0.x, v0.y, v0.z, v0.w, v1.x, v1.y, v1.z, v1.w};
    size_t blob = ((size_t)(m >> 7) * NKC + (k0 >> 6)) * TILE_BYTES;
    cvt8_store(xs, g_X + blob, m & 127u, k0 & 63u);
}

__global__ void __launch_bounds__(256) convW(const float* __restrict__ W,
                                             const float* __restrict__ A1,
                                             const float* __restrict__ B1,
                                             const float* __restrict__ A2,
                                             const float* __restrict__ B2) {
    unsigned idx = blockIdx.x * 256u + threadIdx.x;
    unsigned n  = idx >> 8;
    unsigned k0 = (idx & 255u) << 3;
    const float4* src = (const float4*)(W + (size_t)n * K_ + k0);
    float4 v0 = src[0], v1 = src[1];
    float xs[8] = {v0.x, v0.y, v0.z, v0.w, v1.x, v1.y, v1.z, v1.w};
    if (n >= D_) {
        const float* A;
        const float* Brow;
        if (n < 2 * D_) { A = A1; Brow = B1 + (size_t)(n - D_) * R_; }
        else            { A = A2; Brow = B2 + (size_t)(n - 2 * D_) * R_; }
#pragma unroll
        for (int r = 0; r < R_; r++) {
            float bv = Brow[r];
            const float* Ar = A + (size_t)r * K_ + k0;
#pragma unroll
            for (int j = 0; j < 8; j++) xs[j] = fmaf(bv, Ar[j], xs[j]);
        }
    }
    size_t blob = ((size_t)(n >> 7) * NKC + (k0 >> 6)) * TILE_BYTES;
    cvt8_store(xs, g_W + blob, n & 127u, k0 & 63u);
}

// ---------------------------------------------------------------------------
// GEMM: 128x128 CTA tile, 8 warps (2m x 4n), warp tile 64x32, BK=64,
// 3-stage cp.async pipeline (whole-group prefetch — R9-measured 480us core),
// 2 CTAs/SM (16 warps/SM), fp16 HMMA (m16n8k16), fp32 accumulate.
// ---------------------------------------------------------------------------
__device__ __forceinline__ void issue_chunk(uint32_t st, const unsigned char* ga,
                                            const unsigned char* gb, int tid) {
#pragma unroll
    for (int i = 0; i < 4; i++) {
        uint32_t off = (uint32_t)(i * 256 + tid) * 16u;
        CP_ASYNC16(st + off,          ga + off);
        CP_ASYNC16(st + 16384u + off, gb + off);
    }
}

__global__ void __launch_bounds__(256, 2)
gemm_hmma(const float* __restrict__ bias, float* __restrict__ out) {
    extern __shared__ __align__(16) unsigned char smem_raw[];
    const uint32_t base = (smem_u32(smem_raw) + 1023u) & ~1023u;

    const int tid  = threadIdx.x;
    const int wid  = tid >> 5;
    const int lane = tid & 31;
    const int wm   = wid >> 2;          // 0..1  (64-row slab)
    const int wn   = wid & 3;           // 0..3  (32-col slab)

    const int bn = blockIdx.x;          // 0..47
    const int bm = blockIdx.y;          // 0..63

    const unsigned char* Ab = g_X + (size_t)bm * NKC * TILE_BYTES;
    const unsigned char* Bb = g_W + (size_t)bn * NKC * TILE_BYTES;

    // Per-lane ldmatrix base byte offsets (pre-swizzle) within a tile image.
    const uint32_t a_base = (uint32_t)((wm * 64 + (lane & 15)) * 128 + ((lane >> 4) & 1) * 16);
    // B (x4): mats = {n0-7 k0, n0-7 k1, n8-15 k0, n8-15 k1}
    const uint32_t b_base = (uint32_t)((wn * 32 + (lane & 7) + ((lane >> 4) << 3)) * 128
                                       + ((lane >> 3) & 1) * 16);

    float acc[4][4][4];
#pragma unroll
    for (int i = 0; i < 4; i++)
#pragma unroll
        for (int j = 0; j < 4; j++)
#pragma unroll
            for (int q = 0; q < 4; q++) acc[i][j][q] = 0.0f;

    // Prologue: fill STAGES-1 stages
#pragma unroll
    for (int s = 0; s < STAGES - 1; s++) {
        issue_chunk(base + (uint32_t)s * STAGE_BYTES,
                    Ab + (size_t)s * TILE_BYTES,
                    Bb + (size_t)s * TILE_BYTES, tid);
        CP_COMMIT();
    }

    for (int kc = 0; kc < NKC; kc++) {
        CP_WAIT(STAGES - 2);
        __syncthreads();

        if (kc + STAGES - 1 < NKC) {
            issue_chunk(base + (uint32_t)((kc + STAGES - 1) % STAGES) * STAGE_BYTES,
                        Ab + (size_t)(kc + STAGES - 1) * TILE_BYTES,
                        Bb + (size_t)(kc + STAGES - 1) * TILE_BYTES, tid);
        }
        CP_COMMIT();

        const uint32_t st = base + (uint32_t)(kc % STAGES) * STAGE_BYTES;
        const uint32_t As = st;
        const uint32_t Bs = st + 16384u;

#pragma unroll
        for (int kk = 0; kk < 4; kk++) {
            const uint32_t kb = (uint32_t)kk * 32u;
            uint32_t a[16], b[8];
#pragma unroll
            for (int i = 0; i < 4; i++) {
                uint32_t o = swz(a_base + (uint32_t)i * 2048u + kb);
                LDSM_X4(a[4*i+0], a[4*i+1], a[4*i+2], a[4*i+3], As + o);
            }
#pragma unroll
            for (int g = 0; g < 2; g++) {
                uint32_t o = swz(b_base + (uint32_t)g * 2048u + kb);
                LDSM_X4(b[4*g+0], b[4*g+1], b[4*g+2], b[4*g+3], Bs + o);
            }
#pragma unroll
            for (int i = 0; i < 4; i++) {
#pragma unroll
                for (int j = 0; j < 4; j++) {
                    const int g = j >> 1, h = (j & 1) << 1;
                    MMA_F16(acc[i][j], a[4*i+0], a[4*i+1], a[4*i+2], a[4*i+3],
                            b[4*g+h], b[4*g+h+1]);
                }
            }
        }
    }

    // ---- epilogue: bias + store ----
    const int m0 = bm * 128 + wm * 64;
    const int n0 = bn * 128 + wn * 32;
    const int r  = lane >> 2;
    const int cp = (lane & 3) * 2;

#pragma unroll
    for (int j = 0; j < 4; j++) {
        const int n = n0 + j * 8 + cp;
        const float2 bv = *(const float2*)(bias + n);
#pragma unroll
        for (int i = 0; i < 4; i++) {
            const int row0 = m0 + i * 16 + r;
            float2 o0 = make_float2(acc[i][j][0] + bv.x, acc[i][j][1] + bv.y);
            float2 o1 = make_float2(acc[i][j][2] + bv.x, acc[i][j][3] + bv.y);
            *(float2*)(out + (size_t)row0 * NTOT + n)       = o0;
            *(float2*)(out + (size_t)(row0 + 8) * NTOT + n) = o1;
        }
    }
}

// ---------------------------------------------------------------------------
extern "C" void kernel_launch(void* const* d_in, const int* in_sizes, int n_in,
                              void* d_out, int out_size) {
    const float* x  = (const float*)d_in[0];
    const float* W  = (const float*)d_in[1];
    const float* b  = (const float*)d_in[2];
    const float* A1 = (const float*)d_in[3];
    const float* B1 = (const float*)d_in[4];
    const float* A2 = (const float*)d_in[5];
    const float* B2 = (const float*)d_in[6];
    float* out = (float*)d_out;

    convX<<<M_ * (K_ / 8) / 256, 256>>>(x);
    convW<<<NTOT * (K_ / 8) / 256, 256>>>(W, A1, B1, A2, B2);

    cudaFuncSetAttribute(gemm_hmma, cudaFuncAttributeMaxDynamicSharedMemorySize, SMEM_REQ);
    dim3 grid(NTOT / 128, M_ / 128);   // (48, 64)
    gemm_hmma<<<grid, 256, SMEM_REQ>>>(b, out);
}

// round 13
// speedup vs baseline: 1.0513x; 1.0513x over previous
#include <cuda_runtime.h>
#include <cuda_bf16.h>
#include <cuda_fp16.h>
#include <cstdint>

// ---------------------------------------------------------------------------
// Problem dims (fixed by the dataset)
// ---------------------------------------------------------------------------
#define D_     2048
#define K_     2048
#define NTOT   6144            // 3*D
#define M_     8192            // 4*2048
#define R_     8

#define KC        64           // k-elems per chunk (128B fp16 rows, SW128)
#define NKC       32           // K_/KC
#define MHALVES   64           // M_/128
#define NHALVES   48           // NTOT/128
#define TILE_BYTES  16384      // one 128x64 fp16 tile (SW128 image)
#define STAGES    3
#define STAGE_BYTES 32768      // A (16K) + B (16K)
#define SMEM_REQ  (STAGES * STAGE_BYTES + 1024)   // 99328 -> 2 CTAs/SM

// fp16 blobs, stored as byte-exact SW128 tile images:
// blob[half*32 + kc] = 16KB tile; byte (r, c) at sw128(r*128 + c*2)
__device__ __align__(128) unsigned char g_X[(size_t)MHALVES * NKC * TILE_BYTES]; // 32 MB
__device__ __align__(128) unsigned char g_W[(size_t)NHALVES * NKC * TILE_BYTES]; // 24 MB

// ---------------------------------------------------------------------------
// PTX helpers (baseline sm_80/90 features only)
// ---------------------------------------------------------------------------
__device__ __forceinline__ uint32_t smem_u32(const void* p) {
    uint32_t a;
    asm("{ .reg .u64 t; cvta.to.shared.u64 t, %1; cvt.u32.u64 %0, t; }" : "=r"(a) : "l"(p));
    return a;
}
#define CP_ASYNC16(s, g) \
    asm volatile("cp.async.cg.shared.global [%0], [%1], 16;" :: "r"(s), "l"(g) : "memory")
#define CP_COMMIT() asm volatile("cp.async.commit_group;" ::: "memory")
#define CP_WAIT(n)  asm volatile("cp.async.wait_group %0;" :: "n"(n) : "memory")

#define LDSM_X4(r0, r1, r2, r3, a) \
    asm volatile("ldmatrix.sync.aligned.m8n8.x4.shared.b16 {%0,%1,%2,%3}, [%4];" \
                 : "=r"(r0), "=r"(r1), "=r"(r2), "=r"(r3) : "r"(a))

#define MMA_F16(d, a0, a1, a2, a3, b0, b1) \
    asm volatile("mma.sync.aligned.m16n8k16.row.col.f32.f16.f16.f32 " \
                 "{%0,%1,%2,%3}, {%4,%5,%6,%7}, {%8,%9}, {%0,%1,%2,%3};" \
                 : "+f"((d)[0]), "+f"((d)[1]), "+f"((d)[2]), "+f"((d)[3]) \
                 : "r"(a0), "r"(a1), "r"(a2), "r"(a3), "r"(b0), "r"(b1))

__device__ __forceinline__ uint32_t swz(uint32_t off) { return off ^ ((off >> 3) & 0x70u); }

// ---------------------------------------------------------------------------
// Convert kernels: fp32 -> fp16 in pre-swizzled blob layout.
// ---------------------------------------------------------------------------
__device__ __forceinline__ void cvt8_store(const float* xs, unsigned char* blobbase,
                                           unsigned m_in_half, unsigned k_in_chunk) {
    union { unsigned short s[8]; uint4 v; } h;
#pragma unroll
    for (int j = 0; j < 8; j++) h.s[j] = __half_as_ushort(__float2half_rn(xs[j]));
    unsigned off = (m_in_half << 7) | (k_in_chunk << 1);
    *(uint4*)(blobbase + swz(off)) = h.v;
}

__global__ void __launch_bounds__(256) convX(const float* __restrict__ X) {
    unsigned idx = blockIdx.x * 256u + threadIdx.x;
    unsigned m  = idx >> 8;
    unsigned k0 = (idx & 255u) << 3;
    const float4* src = (const float4*)(X + (size_t)m * K_ + k0);
    float4 v0 = src[0], v1 = src[1];
    float xs[8] = {v0.x, v0.y, v0.z, v0.w, v1.x, v1.y, v1.z, v1.w};
    size_t blob = ((size_t)(m >> 7) * NKC + (k0 >> 6)) * TILE_BYTES;
    cvt8_store(xs, g_X + blob, m & 127u, k0 & 63u);
}

__global__ void __launch_bounds__(256) convW(const float* __restrict__ W,
                                             const float* __restrict__ A1,
                                             const float* __restrict__ B1,
                                             const float* __restrict__ A2,
                                             const float* __restrict__ B2) {
    unsigned idx = blockIdx.x * 256u + threadIdx.x;
    unsigned n  = idx >> 8;
    unsigned k0 = (idx & 255u) << 3;
    const float4* src = (const float4*)(W + (size_t)n * K_ + k0);
    float4 v0 = src[0], v1 = src[1];
    float xs[8] = {v0.x, v0.y, v0.z, v0.w, v1.x, v1.y, v1.z, v1.w};
    if (n >= D_) {
        const float* A;
        const float* Brow;
        if (n < 2 * D_) { A = A1; Brow = B1 + (size_t)(n - D_) * R_; }
        else            { A = A2; Brow = B2 + (size_t)(n - 2 * D_) * R_; }
#pragma unroll
        for (int r = 0; r < R_; r++) {
            float bv = Brow[r];
            const float* Ar = A + (size_t)r * K_ + k0;
#pragma unroll
            for (int j = 0; j < 8; j++) xs[j] = fmaf(bv, Ar[j], xs[j]);
        }
    }
    size_t blob = ((size_t)(n >> 7) * NKC + (k0 >> 6)) * TILE_BYTES;
    cvt8_store(xs, g_W + blob, n & 127u, k0 & 63u);
}

// ---------------------------------------------------------------------------
// GEMM: 128x128 CTA tile, 4 warps (2m x 2n), warp tile 64x64, BK=64,
// 3-stage cp.async pipeline, 2 CTAs/SM, fp16 HMMA, fp32 accumulate.
// NEW vs R8: software-pipelined (double-buffered) operand LDSMs in kk loop.
// ---------------------------------------------------------------------------
__device__ __forceinline__ void issue_chunk(uint32_t st, const unsigned char* ga,
                                            const unsigned char* gb, int tid) {
#pragma unroll
    for (int i = 0; i < 8; i++) {
        uint32_t off = (uint32_t)(i * 128 + tid) * 16u;
        CP_ASYNC16(st + off,          ga + off);
        CP_ASYNC16(st + 16384u + off, gb + off);
    }
}

__global__ void __launch_bounds__(128, 2)
gemm_hmma(const float* __restrict__ bias, float* __restrict__ out) {
    extern __shared__ __align__(16) unsigned char smem_raw[];
    const uint32_t base = (smem_u32(smem_raw) + 1023u) & ~1023u;

    const int tid  = threadIdx.x;
    const int wid  = tid >> 5;
    const int lane = tid & 31;
    const int wm   = wid >> 1;          // 0..1  (64-row slab)
    const int wn   = wid & 1;           // 0..1  (64-col slab)

    const int bn = blockIdx.x;          // 0..47
    const int bm = blockIdx.y;          // 0..63

    const unsigned char* Ab = g_X + (size_t)bm * NKC * TILE_BYTES;
    const unsigned char* Bb = g_W + (size_t)bn * NKC * TILE_BYTES;

    // Per-lane ldmatrix base byte offsets (pre-swizzle) within a tile image.
    const uint32_t a_base = (uint32_t)((wm * 64 + (lane & 15)) * 128 + ((lane >> 4) & 1) * 16);
    const uint32_t b_base = (uint32_t)((wn * 64 + (lane & 7) + ((lane >> 4) << 3)) * 128
                                       + ((lane >> 3) & 1) * 16);

    float acc[4][8][4];
#pragma unroll
    for (int i = 0; i < 4; i++)
#pragma unroll
        for (int j = 0; j < 8; j++)
#pragma unroll
            for (int q = 0; q < 4; q++) acc[i][j][q] = 0.0f;

    // Prologue: fill STAGES-1 stages
#pragma unroll
    for (int s = 0; s < STAGES - 1; s++) {
        issue_chunk(base + (uint32_t)s * STAGE_BYTES,
                    Ab + (size_t)s * TILE_BYTES,
                    Bb + (size_t)s * TILE_BYTES, tid);
        CP_COMMIT();
    }

    uint32_t a[2][16], b[2][16];

    for (int kc = 0; kc < NKC; kc++) {
        CP_WAIT(STAGES - 2);
        __syncthreads();

        if (kc + STAGES - 1 < NKC) {
            issue_chunk(base + (uint32_t)((kc + STAGES - 1) % STAGES) * STAGE_BYTES,
                        Ab + (size_t)(kc + STAGES - 1) * TILE_BYTES,
                        Bb + (size_t)(kc + STAGES - 1) * TILE_BYTES, tid);
        }
        CP_COMMIT();

        const uint32_t st = base + (uint32_t)(kc % STAGES) * STAGE_BYTES;
        const uint32_t As = st;
        const uint32_t Bs = st + 16384u;

        // Preload kk=0 operands
#pragma unroll
        for (int i = 0; i < 4; i++) {
            uint32_t o = swz(a_base + (uint32_t)i * 2048u);
            LDSM_X4(a[0][4*i+0], a[0][4*i+1], a[0][4*i+2], a[0][4*i+3], As + o);
        }
#pragma unroll
        for (int g = 0; g < 4; g++) {
            uint32_t o = swz(b_base + (uint32_t)g * 2048u);
            LDSM_X4(b[0][4*g+0], b[0][4*g+1], b[0][4*g+2], b[0][4*g+3], Bs + o);
        }

#pragma unroll
        for (int kk = 0; kk < 4; kk++) {
            const int cur = kk & 1;
            const int nxt = cur ^ 1;
            if (kk < 3) {
                const uint32_t kb = (uint32_t)(kk + 1) * 32u;
#pragma unroll
                for (int i = 0; i < 4; i++) {
                    uint32_t o = swz(a_base + (uint32_t)i * 2048u + kb);
                    LDSM_X4(a[nxt][4*i+0], a[nxt][4*i+1], a[nxt][4*i+2], a[nxt][4*i+3], As + o);
                }
#pragma unroll
                for (int g = 0; g < 4; g++) {
                    uint32_t o = swz(b_base + (uint32_t)g * 2048u + kb);
                    LDSM_X4(b[nxt][4*g+0], b[nxt][4*g+1], b[nxt][4*g+2], b[nxt][4*g+3], Bs + o);
                }
            }
#pragma unroll
            for (int i = 0; i < 4; i++) {
#pragma unroll
                for (int j = 0; j < 8; j++) {
                    const int g = j >> 1, h = (j & 1) << 1;
                    MMA_F16(acc[i][j], a[cur][4*i+0], a[cur][4*i+1],
                            a[cur][4*i+2], a[cur][4*i+3],
                            b[cur][4*g+h], b[cur][4*g+h+1]);
                }
            }
        }
    }

    // ---- epilogue: bias + store ----
    const int m0 = bm * 128 + wm * 64;
    const int n0 = bn * 128 + wn * 64;
    const int r  = lane >> 2;
    const int cp = (lane & 3) * 2;

#pragma unroll
    for (int j = 0; j < 8; j++) {
        const int n = n0 + j * 8 + cp;
        const float2 bv = *(const float2*)(bias + n);
#pragma unroll
        for (int i = 0; i < 4; i++) {
            const int row0 = m0 + i * 16 + r;
            float2 o0 = make_float2(acc[i][j][0] + bv.x, acc[i][j][1] + bv.y);
            float2 o1 = make_float2(acc[i][j][2] + bv.x, acc[i][j][3] + bv.y);
            *(float2*)(out + (size_t)row0 * NTOT + n)       = o0;
            *(float2*)(out + (size_t)(row0 + 8) * NTOT + n) = o1;
        }
    }
}

// ---------------------------------------------------------------------------
extern "C" void kernel_launch(void* const* d_in, const int* in_sizes, int n_in,
                              void* d_out, int out_size) {
    const float* x  = (const float*)d_in[0];
    const float* W  = (const float*)d_in[1];
    const float* b  = (const float*)d_in[2];
    const float* A1 = (const float*)d_in[3];
    const float* B1 = (const float*)d_in[4];
    const float* A2 = (const float*)d_in[5];
    const float* B2 = (const float*)d_in[6];
    float* out = (float*)d_out;

    convX<<<M_ * (K_ / 8) / 256, 256>>>(x);
    convW<<<NTOT * (K_ / 8) / 256, 256>>>(W, A1, B1, A2, B2);

    cudaFuncSetAttribute(gemm_hmma, cudaFuncAttributeMaxDynamicSharedMemorySize, SMEM_REQ);
    dim3 grid(NTOT / 128, M_ / 128);   // (48, 64)
    gemm_hmma<<<grid, 128, SMEM_REQ>>>(b, out);
}